// round 13
// baseline (speedup 1.0000x reference)
#include <cuda_runtime.h>
#include <cstdint>
#include <math.h>

#define BSN   100
#define CCH   640
#define W_IN  19
#define IMG   (W_IN * W_IN)           // 361
#define NW    5
#define P25   25
#define META_PER_BS (2 * CCH * P25)   // 32000
#define META_TOTAL  (BSN * META_PER_BS)

// Transposed pooled data: [bs][2][p][c]  (c contiguous)
__device__ float scratch_g[(size_t)BSN * 2 * P25 * CCH];   // 12.8 MB
// Arrival counters (self-resetting; zero-initialized at load)
__device__ int cnt_g[BSN];

// ---------------------------------------------------------------------------
// PTX helpers
// ---------------------------------------------------------------------------
__device__ __forceinline__ unsigned long long mk_policy_ef() {
    unsigned long long p;
    asm("createpolicy.fractional.L2::evict_first.b64 %0, 1.0;" : "=l"(p));
    return p;
}
__device__ __forceinline__ unsigned long long mk_policy_el() {
    unsigned long long p;
    asm("createpolicy.fractional.L2::evict_last.b64 %0, 1.0;" : "=l"(p));
    return p;
}
__device__ __forceinline__ void cp_async16_ef(unsigned int saddr,
                                              const void* gptr,
                                              unsigned long long pol) {
    asm volatile("cp.async.cg.shared.global.L2::cache_hint [%0], [%1], 16, %2;\n"
                 :: "r"(saddr), "l"(gptr), "l"(pol));
}
__device__ __forceinline__ void cp_commit() {
    asm volatile("cp.async.commit_group;\n");
}
template<int N>
__device__ __forceinline__ void cp_wait() {
    asm volatile("cp.async.wait_group %0;\n" :: "n"(N));
}
__device__ __forceinline__ unsigned int s2u(const void* p) {
    return (unsigned int)__cvta_generic_to_shared(p);
}
__device__ __forceinline__ void stg_hint(float* p, float v,
                                         unsigned long long pol) {
    asm volatile("st.global.L2::cache_hint.f32 [%0], %1, %2;"
                 :: "l"(p), "f"(v), "l"(pol));
}

// ===========================================================================
// Single fused kernel: pool (cp.async pipelined) + last-block-per-bs cosine.
// 2000 blocks x 64 images; 8 chunks of 8 images; double-buffered smem.
// ===========================================================================
#define IMGS_CHUNK 8
#define CHUNK_FLOATS (IMGS_CHUNK * IMG)    // 2888
#define CHUNK_N4 (CHUNK_FLOATS / 4)        // 722 = 5*128 + 82
#define POOL_THREADS 128
#define POOL_FULL 5
#define N_CHUNKS 8
#define SA_FLOATS (IMGS_CHUNK * W_IN * NW) // 760

__global__ __launch_bounds__(POOL_THREADS, 6) void pool_kernel(
    const float* __restrict__ s_in,
    const float* __restrict__ q_in,
    float* __restrict__ out)
{
    __shared__ float buf0[CHUNK_FLOATS];
    __shared__ float buf1[CHUNK_FLOATS];
    __shared__ float sA[SA_FLOATS];
    __shared__ int tkt_sh;

    const int blk = blockIdx.x;                // 0..1999
    const int tid = threadIdx.x;
    const int sel = (blk >= 1000) ? 1 : 0;
    const int lblk = blk - sel * 1000;

    const unsigned long long pol_ef = mk_policy_ef();
    const unsigned long long pol_el = mk_policy_el();

    const float* __restrict__ gsrc =
        (sel ? q_in : s_in) + (size_t)lblk * (64 * IMG);

    const int img0 = lblk * 64;
    const int bs = img0 / CCH;
    const int c0 = img0 - bs * CCH;
    float* __restrict__ meta_base =
        out + (size_t)bs * META_PER_BS + (size_t)(sel * CCH + c0) * P25;
    float* __restrict__ scr_base =
        scratch_g + ((size_t)(bs * 2 + sel) * P25) * CCH;

#define PF(CK, BUF)                                                          \
    do {                                                                     \
        const float4* _g = (const float4*)(gsrc + (CK) * CHUNK_FLOATS);      \
        unsigned int _s = s2u(BUF);                                          \
        _Pragma("unroll")                                                    \
        for (int _k = 0; _k < POOL_FULL; _k++)                               \
            cp_async16_ef(_s + (tid + _k * POOL_THREADS) * 16,               \
                          _g + tid + _k * POOL_THREADS, pol_ef);             \
        if (tid < CHUNK_N4 - POOL_FULL * POOL_THREADS)                       \
            cp_async16_ef(_s + (POOL_FULL * POOL_THREADS + tid) * 16,        \
                          _g + POOL_FULL * POOL_THREADS + tid, pol_ef);      \
        cp_commit();                                                         \
    } while (0)

    PF(0, buf0);

#pragma unroll
    for (int ck = 0; ck < N_CHUNKS; ck++) {
        if (ck + 1 < N_CHUNKS) {
            if ((ck + 1) & 1) PF(ck + 1, buf1); else PF(ck + 1, buf0);
            cp_wait<1>();
        } else {
            cp_wait<0>();
        }
        __syncthreads();

        const float* __restrict__ cbuf = (ck & 1) ? buf1 : buf0;

        // ---- stage A: column-bin rows. 152 tasks ----
        {
            const int idx = tid;
            if (idx < IMGS_CHUNK * W_IN) {
                const float* __restrict__ row = cbuf + idx * W_IN;
                float r[W_IN];
#pragma unroll
                for (int w = 0; w < W_IN; w++) r[w] = row[w];
                const int BS_[NW] = {0, 3, 7, 11, 15};
                const int BE_[NW] = {4, 8, 12, 16, 19};
#pragma unroll
                for (int j = 0; j < NW; j++) {
                    float v = 0.0f;
#pragma unroll
                    for (int w = BS_[j]; w < BE_[j]; w++) v += r[w];
                    sA[idx * NW + j] = v;
                }
            }
            const int idx2 = tid + POOL_THREADS;
            if (idx2 < IMGS_CHUNK * W_IN) {
                const float* __restrict__ row = cbuf + idx2 * W_IN;
                float r[W_IN];
#pragma unroll
                for (int w = 0; w < W_IN; w++) r[w] = row[w];
                const int BS_[NW] = {0, 3, 7, 11, 15};
                const int BE_[NW] = {4, 8, 12, 16, 19};
#pragma unroll
                for (int j = 0; j < NW; j++) {
                    float v = 0.0f;
#pragma unroll
                    for (int w = BS_[j]; w < BE_[j]; w++) v += r[w];
                    sA[idx2 * NW + j] = v;
                }
            }
        }
        __syncthreads();

        // ---- stage B: row-bin + scale; meta + scratch ----
        const int cc0 = c0 + ck * IMGS_CHUNK;
        float* __restrict__ mdst = meta_base + (size_t)ck * IMGS_CHUNK * P25;
#pragma unroll
        for (int base = 0; base < IMGS_CHUNK * P25; base += POOL_THREADS) {
            const int idx = base + tid;
            if (idx < IMGS_CHUNK * P25) {
                const int img = idx / P25;
                const int o = idx - img * P25;
                const int i = o / NW;
                const int j = o - i * NW;
                const int rs = (19 * i) / 5;
                const int leni = (19 * i + 23) / 5 - rs;
                const int lenj = (19 * j + 23) / 5 - (19 * j) / 5;
                const float* __restrict__ a = sA + (img * W_IN + rs) * NW + j;
                float v = a[0] + a[1 * NW] + a[2 * NW] + a[3 * NW];
                if (leni == 5) v += a[4 * NW];
                const float invi = (leni == 4) ? 0.25f : 0.2f;
                const float invj = (lenj == 4) ? 0.25f : 0.2f;
                v = v * invi * invj;
                stg_hint(mdst + idx, v, pol_ef);
                stg_hint(scr_base + (size_t)o * CCH + cc0 + img, v, pol_el);
            }
        }
    }
#undef PF

    // ===================== last-block-per-bs cosine ========================
    __threadfence();            // make this block's scratch stores visible
    __syncthreads();
    if (tid == 0) tkt_sh = atomicAdd(&cnt_g[bs], 1);
    __syncthreads();

    if (tkt_sh == 19) {         // 20th (last) block for this bs does the dots
        float* __restrict__ simbuf = buf0;   // reuse: 625 <= 2888 floats
        const float* __restrict__ sb =
            scratch_g + (size_t)(bs * 2 + 0) * P25 * CCH;
        const float* __restrict__ qb =
            scratch_g + (size_t)(bs * 2 + 1) * P25 * CCH;
        const int w = tid >> 5;
        const int lane = tid & 31;

        for (int tile = w; tile < P25; tile += 4) {
            const int tp = tile / NW;
            const int pg = tp * NW;
            const int qg = (tile - tp * NW) * NW;

            float acc[NW][NW];
            float ssq[NW], qsq[NW];
#pragma unroll
            for (int i = 0; i < NW; i++) {
                ssq[i] = 0.0f; qsq[i] = 0.0f;
#pragma unroll
                for (int j = 0; j < NW; j++) acc[i][j] = 0.0f;
            }

#pragma unroll
            for (int k = 0; k < CCH / 128; k++) {
                const int c = k * 128 + lane * 4;
                float4 sv[NW];
#pragma unroll
                for (int i = 0; i < NW; i++)
                    sv[i] = *(const float4*)(sb + (size_t)(pg + i) * CCH + c);
#pragma unroll
                for (int i = 0; i < NW; i++) {
                    ssq[i] = fmaf(sv[i].x, sv[i].x, ssq[i]);
                    ssq[i] = fmaf(sv[i].y, sv[i].y, ssq[i]);
                    ssq[i] = fmaf(sv[i].z, sv[i].z, ssq[i]);
                    ssq[i] = fmaf(sv[i].w, sv[i].w, ssq[i]);
                }
#pragma unroll
                for (int j = 0; j < NW; j++) {
                    const float4 qv =
                        *(const float4*)(qb + (size_t)(qg + j) * CCH + c);
                    qsq[j] = fmaf(qv.x, qv.x, qsq[j]);
                    qsq[j] = fmaf(qv.y, qv.y, qsq[j]);
                    qsq[j] = fmaf(qv.z, qv.z, qsq[j]);
                    qsq[j] = fmaf(qv.w, qv.w, qsq[j]);
#pragma unroll
                    for (int i = 0; i < NW; i++) {
                        float a = acc[i][j];
                        a = fmaf(sv[i].x, qv.x, a);
                        a = fmaf(sv[i].y, qv.y, a);
                        a = fmaf(sv[i].z, qv.z, a);
                        a = fmaf(sv[i].w, qv.w, a);
                        acc[i][j] = a;
                    }
                }
            }

            // warp reduce 35 values
#pragma unroll
            for (int off = 16; off; off >>= 1) {
#pragma unroll
                for (int i = 0; i < NW; i++) {
                    ssq[i] += __shfl_down_sync(0xffffffffu, ssq[i], off);
                    qsq[i] += __shfl_down_sync(0xffffffffu, qsq[i], off);
#pragma unroll
                    for (int j = 0; j < NW; j++)
                        acc[i][j] += __shfl_down_sync(0xffffffffu, acc[i][j], off);
                }
            }

            if (lane == 0) {
                float qn[NW];
#pragma unroll
                for (int j = 0; j < NW; j++) qn[j] = sqrtf(qsq[j]);
#pragma unroll
                for (int i = 0; i < NW; i++) {
                    const float snp = sqrtf(ssq[i]);
#pragma unroll
                    for (int j = 0; j < NW; j++) {
                        const float den = fmaxf(snp * qn[j], 1e-8f);
                        simbuf[(pg + i) * P25 + (qg + j)] = acc[i][j] / den;
                    }
                }
            }
        }
        __syncthreads();

        if (tid < P25) {
            float m = -INFINITY;
#pragma unroll
            for (int q = 0; q < P25; q++)
                m = fmaxf(m, simbuf[tid * P25 + q]);
            out[META_TOTAL + bs * P25 + tid] = m;
        }
        if (tid == 0) cnt_g[bs] = 0;   // reset for next launch / graph replay
    }
}

extern "C" void kernel_launch(void* const* d_in, const int* in_sizes, int n_in,
                              void* d_out, int out_size)
{
    const float* s_in = (const float*)d_in[0];
    const float* q_in = (const float*)d_in[1];
    float* out = (float*)d_out;

    pool_kernel<<<2000, POOL_THREADS>>>(s_in, q_in, out);
}

// round 14
// speedup vs baseline: 1.8825x; 1.8825x over previous
#include <cuda_runtime.h>
#include <cstdint>
#include <math.h>

#define BSN   100
#define CCH   640
#define W_IN  19
#define IMG   (W_IN * W_IN)           // 361
#define NW    5
#define P25   25
#define META_PER_BS (2 * CCH * P25)   // 32000
#define META_TOTAL  (BSN * META_PER_BS)

// Per-bs accumulators: 625 dots, then 25 ssq, then 25 qsq  (zero-init at load;
// finish_kernel re-zeroes after each use so graph replays see zeros)
#define ACC_PER_BS 675
__device__ float dacc_g[BSN * ACC_PER_BS];

// ---------------------------------------------------------------------------
// PTX helpers
// ---------------------------------------------------------------------------
__device__ __forceinline__ unsigned long long mk_policy_ef() {
    unsigned long long p;
    asm("createpolicy.fractional.L2::evict_first.b64 %0, 1.0;" : "=l"(p));
    return p;
}
__device__ __forceinline__ void cp_async16_ef(unsigned int saddr,
                                              const void* gptr,
                                              unsigned long long pol) {
    asm volatile("cp.async.cg.shared.global.L2::cache_hint [%0], [%1], 16, %2;\n"
                 :: "r"(saddr), "l"(gptr), "l"(pol));
}
__device__ __forceinline__ void cp_commit() {
    asm volatile("cp.async.commit_group;\n");
}
template<int N>
__device__ __forceinline__ void cp_wait() {
    asm volatile("cp.async.wait_group %0;\n" :: "n"(N));
}
__device__ __forceinline__ unsigned int s2u(const void* p) {
    return (unsigned int)__cvta_generic_to_shared(p);
}
__device__ __forceinline__ void stg_hint(float* p, float v,
                                         unsigned long long pol) {
    asm volatile("st.global.L2::cache_hint.f32 [%0], %1, %2;"
                 :: "l"(p), "f"(v), "l"(pol));
}

// ===========================================================================
// Kernel 1: pool + partial dots.
// 2000 blocks; block (bs, seg) owns channels [seg*32, seg*32+32) of BOTH
// s and q for one bs. 8 chunks of 8 images (0-3 from s, 4-7 from q),
// double-buffered cp.async. After pooling: uniform in-block partial dots
// over the local 32 channels, accumulated via atomicAdd (REDG).
// ===========================================================================
#define IMGS_CHUNK 8
#define CHUNK_FLOATS (IMGS_CHUNK * IMG)    // 2888
#define CHUNK_N4 (CHUNK_FLOATS / 4)        // 722 = 5*128 + 82
#define POOL_THREADS 128
#define POOL_FULL 5
#define N_CHUNKS 8
#define SA_FLOATS (IMGS_CHUNK * W_IN * NW) // 760
#define SEGC 32                            // channels per tensor per block

__global__ __launch_bounds__(POOL_THREADS, 7) void pool_kernel(
    const float* __restrict__ s_in,
    const float* __restrict__ q_in,
    float* __restrict__ out)
{
    __shared__ float buf0[CHUNK_FLOATS];
    __shared__ float buf1[CHUNK_FLOATS];
    __shared__ float sA[SA_FLOATS];
    __shared__ float pooled[2 * SEGC * P25];   // [t][cl][o], c-major rows

    const int blk = blockIdx.x;                // 0..1999
    const int tid = threadIdx.x;
    const int bs  = blk / 20;
    const int seg = blk - bs * 20;
    const int c0  = seg * SEGC;

    const unsigned long long pol_ef = mk_policy_ef();

    const float* __restrict__ gsrc_s =
        s_in + ((size_t)bs * CCH + c0) * IMG;
    const float* __restrict__ gsrc_q =
        q_in + ((size_t)bs * CCH + c0) * IMG;

#define PF(CK, BUF)                                                          \
    do {                                                                     \
        const float* _base = ((CK) < 4)                                      \
            ? (gsrc_s + (CK) * CHUNK_FLOATS)                                 \
            : (gsrc_q + ((CK) - 4) * CHUNK_FLOATS);                          \
        const float4* _g = (const float4*)_base;                             \
        unsigned int _s = s2u(BUF);                                          \
        _Pragma("unroll")                                                    \
        for (int _k = 0; _k < POOL_FULL; _k++)                               \
            cp_async16_ef(_s + (tid + _k * POOL_THREADS) * 16,               \
                          _g + tid + _k * POOL_THREADS, pol_ef);             \
        if (tid < CHUNK_N4 - POOL_FULL * POOL_THREADS)                       \
            cp_async16_ef(_s + (POOL_FULL * POOL_THREADS + tid) * 16,        \
                          _g + POOL_FULL * POOL_THREADS + tid, pol_ef);      \
        cp_commit();                                                         \
    } while (0)

    PF(0, buf0);

#pragma unroll
    for (int ck = 0; ck < N_CHUNKS; ck++) {
        if (ck + 1 < N_CHUNKS) {
            if ((ck + 1) & 1) PF(ck + 1, buf1); else PF(ck + 1, buf0);
            cp_wait<1>();
        } else {
            cp_wait<0>();
        }
        __syncthreads();

        const float* __restrict__ cbuf = (ck & 1) ? buf1 : buf0;

        // ---- stage A: column-bin rows. 152 tasks ----
        {
            const int idx = tid;
            if (idx < IMGS_CHUNK * W_IN) {
                const float* __restrict__ row = cbuf + idx * W_IN;
                float r[W_IN];
#pragma unroll
                for (int w = 0; w < W_IN; w++) r[w] = row[w];
                const int BS_[NW] = {0, 3, 7, 11, 15};
                const int BE_[NW] = {4, 8, 12, 16, 19};
#pragma unroll
                for (int j = 0; j < NW; j++) {
                    float v = 0.0f;
#pragma unroll
                    for (int w = BS_[j]; w < BE_[j]; w++) v += r[w];
                    sA[idx * NW + j] = v;
                }
            }
            const int idx2 = tid + POOL_THREADS;
            if (idx2 < IMGS_CHUNK * W_IN) {
                const float* __restrict__ row = cbuf + idx2 * W_IN;
                float r[W_IN];
#pragma unroll
                for (int w = 0; w < W_IN; w++) r[w] = row[w];
                const int BS_[NW] = {0, 3, 7, 11, 15};
                const int BE_[NW] = {4, 8, 12, 16, 19};
#pragma unroll
                for (int j = 0; j < NW; j++) {
                    float v = 0.0f;
#pragma unroll
                    for (int w = BS_[j]; w < BE_[j]; w++) v += r[w];
                    sA[idx2 * NW + j] = v;
                }
            }
        }
        __syncthreads();

        // ---- stage B: row-bin + scale; write meta + pooled(smem) ----
        const int t   = (ck >= 4) ? 1 : 0;
        const int lck = ck - t * 4;           // chunk within tensor, 0..3
        float* __restrict__ mdst = out + (size_t)bs * META_PER_BS
            + (size_t)(t * CCH + c0 + lck * IMGS_CHUNK) * P25;
#pragma unroll
        for (int base = 0; base < IMGS_CHUNK * P25; base += POOL_THREADS) {
            const int idx = base + tid;
            if (idx < IMGS_CHUNK * P25) {
                const int img = idx / P25;
                const int o = idx - img * P25;
                const int i = o / NW;
                const int j = o - i * NW;
                const int rs = (19 * i) / 5;
                const int leni = (19 * i + 23) / 5 - rs;
                const int lenj = (19 * j + 23) / 5 - (19 * j) / 5;
                const float* __restrict__ a = sA + (img * W_IN + rs) * NW + j;
                float v = a[0] + a[1 * NW] + a[2 * NW] + a[3 * NW];
                if (leni == 5) v += a[4 * NW];
                const float invi = (leni == 4) ? 0.25f : 0.2f;
                const float invj = (lenj == 4) ? 0.25f : 0.2f;
                v = v * invi * invj;
                stg_hint(mdst + idx, v, pol_ef);
                // pooled[t][cl][o], cl = local channel 0..31
                pooled[(t * SEGC + lck * IMGS_CHUNK + img) * P25 + o] = v;
            }
        }
    }
#undef PF
    __syncthreads();   // pooled tile complete

    // ---- uniform partial dots over local 32 channels (from smem) ----
    float* __restrict__ dst = dacc_g + bs * ACC_PER_BS;
    for (int p = tid; p < P25 * P25; p += POOL_THREADS) {
        const int i = p / P25;
        const int j = p - i * P25;
        float d = 0.0f;
#pragma unroll
        for (int cl = 0; cl < SEGC; cl++)
            d = fmaf(pooled[cl * P25 + i],
                     pooled[(SEGC + cl) * P25 + j], d);
        atomicAdd(dst + p, d);
    }
    if (tid < 2 * P25) {
        const int t = tid / P25;
        const int o = tid - t * P25;
        float s = 0.0f;
#pragma unroll
        for (int cl = 0; cl < SEGC; cl++) {
            const float x = pooled[(t * SEGC + cl) * P25 + o];
            s = fmaf(x, x, s);
        }
        atomicAdd(dst + P25 * P25 + tid, s);
    }
}

// ===========================================================================
// Kernel 2: finisher. 100 blocks; sqrt + divide + max; self-resets dacc_g.
// ===========================================================================
__global__ __launch_bounds__(128) void finish_kernel(float* __restrict__ out)
{
    __shared__ float sn[2 * P25];
    __shared__ float simbuf[P25 * P25];

    const int bs = blockIdx.x;
    const int tid = threadIdx.x;
    float* __restrict__ acc = dacc_g + bs * ACC_PER_BS;

    if (tid < 2 * P25) sn[tid] = sqrtf(acc[P25 * P25 + tid]);
    __syncthreads();

    for (int p = tid; p < P25 * P25; p += 128) {
        const int i = p / P25;
        const int j = p - i * P25;
        simbuf[p] = acc[p] / fmaxf(sn[i] * sn[P25 + j], 1e-8f);
    }
    __syncthreads();

    // reset accumulators for the next launch / graph replay
    for (int k = tid; k < ACC_PER_BS; k += 128) acc[k] = 0.0f;

    if (tid < P25) {
        float m = -INFINITY;
#pragma unroll
        for (int q = 0; q < P25; q++)
            m = fmaxf(m, simbuf[tid * P25 + q]);
        out[META_TOTAL + bs * P25 + tid] = m;
    }
}

extern "C" void kernel_launch(void* const* d_in, const int* in_sizes, int n_in,
                              void* d_out, int out_size)
{
    const float* s_in = (const float*)d_in[0];
    const float* q_in = (const float*)d_in[1];
    float* out = (float*)d_out;

    pool_kernel<<<2000, POOL_THREADS>>>(s_in, q_in, out);
    finish_kernel<<<BSN, 128>>>(out);
}

// round 15
// speedup vs baseline: 2.0804x; 1.1051x over previous
#include <cuda_runtime.h>
#include <cstdint>
#include <math.h>

#define BSN   100
#define CCH   640
#define W_IN  19
#define IMG   (W_IN * W_IN)           // 361
#define NW    5
#define P25   25
#define META_PER_BS (2 * CCH * P25)   // 32000
#define META_TOTAL  (BSN * META_PER_BS)

// Per-bs accumulators: 625 dots, then 25 ssq, then 25 qsq  (zero-init at load;
// finish_kernel re-zeroes after each use so graph replays see zeros)
#define ACC_PER_BS 675
__device__ float dacc_g[BSN * ACC_PER_BS];

// ---------------------------------------------------------------------------
// PTX helpers
// ---------------------------------------------------------------------------
__device__ __forceinline__ unsigned long long mk_policy_ef() {
    unsigned long long p;
    asm("createpolicy.fractional.L2::evict_first.b64 %0, 1.0;" : "=l"(p));
    return p;
}
__device__ __forceinline__ void cp_async16_ef(unsigned int saddr,
                                              const void* gptr,
                                              unsigned long long pol) {
    asm volatile("cp.async.cg.shared.global.L2::cache_hint [%0], [%1], 16, %2;\n"
                 :: "r"(saddr), "l"(gptr), "l"(pol));
}
__device__ __forceinline__ void cp_commit() {
    asm volatile("cp.async.commit_group;\n");
}
template<int N>
__device__ __forceinline__ void cp_wait() {
    asm volatile("cp.async.wait_group %0;\n" :: "n"(N));
}
__device__ __forceinline__ unsigned int s2u(const void* p) {
    return (unsigned int)__cvta_generic_to_shared(p);
}
__device__ __forceinline__ void stg_hint(float* p, float v,
                                         unsigned long long pol) {
    asm volatile("st.global.L2::cache_hint.f32 [%0], %1, %2;"
                 :: "l"(p), "f"(v), "l"(pol));
}

// ===========================================================================
// Kernel 1: pool + partial dots.
// 2000 blocks; block (bs, seg) owns channels [seg*32, seg*32+32) of BOTH
// s and q for one bs. 8 chunks of 8 images (0-3 s, 4-7 q), double-buffered
// cp.async. Tail: uniform partial dots (125 thr x 5 pairs, sv reuse) +
// norms, accumulated via atomicAdd.
// ===========================================================================
#define IMGS_CHUNK 8
#define CHUNK_FLOATS (IMGS_CHUNK * IMG)    // 2888
#define CHUNK_N4 (CHUNK_FLOATS / 4)        // 722 = 5*128 + 82
#define POOL_THREADS 128
#define POOL_FULL 5
#define N_CHUNKS 8
#define SA_FLOATS (IMGS_CHUNK * W_IN * NW) // 760
#define SEGC 32                            // channels per tensor per block

__global__ __launch_bounds__(POOL_THREADS, 7) void pool_kernel(
    const float* __restrict__ s_in,
    const float* __restrict__ q_in,
    float* __restrict__ out)
{
    __shared__ float buf0[CHUNK_FLOATS];
    __shared__ float buf1[CHUNK_FLOATS];
    __shared__ float sA[SA_FLOATS];
    __shared__ float pooled[2 * SEGC * P25];   // [t][cl][o]

    const int blk = blockIdx.x;                // 0..1999
    const int tid = threadIdx.x;
    const int bs  = blk / 20;
    const int seg = blk - bs * 20;
    const int c0  = seg * SEGC;

    const unsigned long long pol_ef = mk_policy_ef();

    const float* __restrict__ gsrc_s =
        s_in + ((size_t)bs * CCH + c0) * IMG;
    const float* __restrict__ gsrc_q =
        q_in + ((size_t)bs * CCH + c0) * IMG;

#define PF(CK, BUF)                                                          \
    do {                                                                     \
        const float* _base = ((CK) < 4)                                      \
            ? (gsrc_s + (CK) * CHUNK_FLOATS)                                 \
            : (gsrc_q + ((CK) - 4) * CHUNK_FLOATS);                          \
        const float4* _g = (const float4*)_base;                             \
        unsigned int _s = s2u(BUF);                                          \
        _Pragma("unroll")                                                    \
        for (int _k = 0; _k < POOL_FULL; _k++)                               \
            cp_async16_ef(_s + (tid + _k * POOL_THREADS) * 16,               \
                          _g + tid + _k * POOL_THREADS, pol_ef);             \
        if (tid < CHUNK_N4 - POOL_FULL * POOL_THREADS)                       \
            cp_async16_ef(_s + (POOL_FULL * POOL_THREADS + tid) * 16,        \
                          _g + POOL_FULL * POOL_THREADS + tid, pol_ef);      \
        cp_commit();                                                         \
    } while (0)

    PF(0, buf0);

#pragma unroll
    for (int ck = 0; ck < N_CHUNKS; ck++) {
        if (ck + 1 < N_CHUNKS) {
            if ((ck + 1) & 1) PF(ck + 1, buf1); else PF(ck + 1, buf0);
            cp_wait<1>();
        } else {
            cp_wait<0>();
        }
        __syncthreads();

        const float* __restrict__ cbuf = (ck & 1) ? buf1 : buf0;

        // ---- stage A: column-bin rows. 152 tasks ----
        {
            const int idx = tid;
            if (idx < IMGS_CHUNK * W_IN) {
                const float* __restrict__ row = cbuf + idx * W_IN;
                float r[W_IN];
#pragma unroll
                for (int w = 0; w < W_IN; w++) r[w] = row[w];
                const int BS_[NW] = {0, 3, 7, 11, 15};
                const int BE_[NW] = {4, 8, 12, 16, 19};
#pragma unroll
                for (int j = 0; j < NW; j++) {
                    float v = 0.0f;
#pragma unroll
                    for (int w = BS_[j]; w < BE_[j]; w++) v += r[w];
                    sA[idx * NW + j] = v;
                }
            }
            const int idx2 = tid + POOL_THREADS;
            if (idx2 < IMGS_CHUNK * W_IN) {
                const float* __restrict__ row = cbuf + idx2 * W_IN;
                float r[W_IN];
#pragma unroll
                for (int w = 0; w < W_IN; w++) r[w] = row[w];
                const int BS_[NW] = {0, 3, 7, 11, 15};
                const int BE_[NW] = {4, 8, 12, 16, 19};
#pragma unroll
                for (int j = 0; j < NW; j++) {
                    float v = 0.0f;
#pragma unroll
                    for (int w = BS_[j]; w < BE_[j]; w++) v += r[w];
                    sA[idx2 * NW + j] = v;
                }
            }
        }
        __syncthreads();

        // ---- stage B: row-bin + scale; write meta + pooled(smem) ----
        const int t   = (ck >= 4) ? 1 : 0;
        const int lck = ck - t * 4;
        float* __restrict__ mdst = out + (size_t)bs * META_PER_BS
            + (size_t)(t * CCH + c0 + lck * IMGS_CHUNK) * P25;
#pragma unroll
        for (int base = 0; base < IMGS_CHUNK * P25; base += POOL_THREADS) {
            const int idx = base + tid;
            if (idx < IMGS_CHUNK * P25) {
                const int img = idx / P25;
                const int o = idx - img * P25;
                const int i = o / NW;
                const int j = o - i * NW;
                const int rs = (19 * i) / 5;
                const int leni = (19 * i + 23) / 5 - rs;
                const int lenj = (19 * j + 23) / 5 - (19 * j) / 5;
                const float* __restrict__ a = sA + (img * W_IN + rs) * NW + j;
                float v = a[0] + a[1 * NW] + a[2 * NW] + a[3 * NW];
                if (leni == 5) v += a[4 * NW];
                const float invi = (leni == 4) ? 0.25f : 0.2f;
                const float invj = (lenj == 4) ? 0.25f : 0.2f;
                v = v * invi * invj;
                stg_hint(mdst + idx, v, pol_ef);
                pooled[(t * SEGC + lck * IMGS_CHUNK + img) * P25 + o] = v;
            }
        }
    }
#undef PF
    __syncthreads();   // pooled tile complete

    // ---- partial dots: 125 threads x 5 pairs (same i -> sv reuse) ----
    float* __restrict__ dst = dacc_g + bs * ACC_PER_BS;
    if (tid < 125) {
        const int i  = tid / NW;
        const int j0 = (tid - i * NW) * NW;
        float d[NW];
#pragma unroll
        for (int k = 0; k < NW; k++) d[k] = 0.0f;
#pragma unroll
        for (int cl = 0; cl < SEGC; cl++) {
            const float s = pooled[cl * P25 + i];
            const float* __restrict__ qrow = pooled + (SEGC + cl) * P25 + j0;
#pragma unroll
            for (int k = 0; k < NW; k++)
                d[k] = fmaf(s, qrow[k], d[k]);
        }
#pragma unroll
        for (int k = 0; k < NW; k++)
            atomicAdd(dst + i * P25 + j0 + k, d[k]);
    }
    if (tid < 2 * P25) {
        const int t = tid / P25;
        const int o = tid - t * P25;
        float s = 0.0f;
#pragma unroll
        for (int cl = 0; cl < SEGC; cl++) {
            const float x = pooled[(t * SEGC + cl) * P25 + o];
            s = fmaf(x, x, s);
        }
        atomicAdd(dst + P25 * P25 + tid, s);
    }
}

// ===========================================================================
// Kernel 2: finisher. 100 blocks x 800 threads; warp = output p, lane = q.
// Critical path: one round of independent L2 loads + 5 shuffle-max rounds.
// Self-resets dacc_g after a sync.
// ===========================================================================
__global__ __launch_bounds__(800) void finish_kernel(float* __restrict__ out)
{
    const int bs = blockIdx.x;
    const int tid = threadIdx.x;
    const int p = tid >> 5;            // 0..24
    const int lane = tid & 31;
    float* __restrict__ acc = dacc_g + bs * ACC_PER_BS;

    float r = -INFINITY;
    {
        // all lanes issue their loads up front (independent)
        const int q = (lane < P25) ? lane : 0;
        const float d   = acc[p * P25 + q];
        const float ssq = acc[P25 * P25 + p];          // broadcast within warp
        const float qsq = acc[P25 * P25 + P25 + q];
        const float den = fmaxf(sqrtf(ssq) * sqrtf(qsq), 1e-8f);
        const float v = d / den;
        r = (lane < P25) ? v : -INFINITY;
    }
#pragma unroll
    for (int off = 16; off; off >>= 1)
        r = fmaxf(r, __shfl_xor_sync(0xffffffffu, r, off));
    if (lane == 0)
        out[META_TOTAL + bs * P25 + p] = r;

    __syncthreads();                   // all reads of acc done
    for (int k = tid; k < ACC_PER_BS; k += 800) acc[k] = 0.0f;
}

extern "C" void kernel_launch(void* const* d_in, const int* in_sizes, int n_in,
                              void* d_out, int out_size)
{
    const float* s_in = (const float*)d_in[0];
    const float* q_in = (const float*)d_in[1];
    float* out = (float*)d_out;

    pool_kernel<<<2000, POOL_THREADS>>>(s_in, q_in, out);
    finish_kernel<<<BSN, 800>>>(out);
}